// round 4
// baseline (speedup 1.0000x reference)
#include <cuda_runtime.h>
#include <math.h>

#define BATCH 32
#define NV 1556
#define NI 256
#define NTOK 1812      // NV + NI
#define DM 512
#define IMGD 2048

static_assert((BATCH * NTOK) % 128 == 0, "token rows must tile by 128");
static_assert((BATCH * NV) % 128 == 0, "vert rows must tile by 128");
static_assert((BATCH * NI) % 128 == 0, "img rows must tile by 128");

#define SOFTMAX_SCALE 0.088388347648318440550f  // (512/4)^-0.5

// Scratch (device-global: no runtime allocation allowed).
// g_X doubles as: x = concat(verts, img_proj)  [B*NTOK, DM]
//                 then (after q/k consumed) the proj-GEMM output [B*NV, DM]
__device__ float g_X[BATCH * NTOK * DM];
__device__ float g_Q[BATCH * NTOK * DM];
__device__ float g_K[BATCH * NTOK * DM];
__device__ float g_G[BATCH * DM];

// ---------------------------------------------------------------------------
// Copy verts_f into the first NV token rows of X (float4 granularity).
// ---------------------------------------------------------------------------
__global__ void __launch_bounds__(256) copy_verts_k(const float* __restrict__ V) {
    size_t i = (size_t)blockIdx.x * 256 + threadIdx.x;       // float4 index
    const size_t tot = (size_t)BATCH * NV * (DM / 4);
    if (i >= tot) return;
    size_t m = i >> 7;               // row (DM/4 = 128 float4 per row)
    int c = (int)(i & 127);
    int b = (int)(m / NV);
    int n = (int)(m - (size_t)b * NV);
    reinterpret_cast<float4*>(g_X)[((size_t)b * NTOK + n) * (DM / 4) + c] =
        reinterpret_cast<const float4*>(V)[i];
}

// ---------------------------------------------------------------------------
// Tiled SGEMM: C[M, 512] = A[M, K] @ W[512, K]^T + bias, with fused variants.
//   MODE 0: A = img_f; C rows remapped into X's img-token slots.
//   MODE 1: plain (q / k projections, X -> Q or K).
//   MODE 2: A_eff[m,k] = g[b][k] * K[b*NTOK+n, k]  (m = b*NV+n);
//           epilogue += Q[b*NTOK+n, col]; C compact rows.
//   MODE 3: A = compact temp; epilogue += verts residual; C = d_out.
// Tile 128x128xBK16, 256 threads, 8x8 per thread, double-buffered smem.
// ---------------------------------------------------------------------------
template <int MODE>
__global__ void __launch_bounds__(256) gemm_k(
    const float* __restrict__ A, const float* __restrict__ W,
    const float* __restrict__ bias, float* __restrict__ C,
    int K,
    const float* __restrict__ E0, const float* __restrict__ E1)
{
    __shared__ float As[2][16][128];
    __shared__ float Bs[2][16][128];

    const int tid  = threadIdx.x;
    const int row0 = blockIdx.y * 128;
    const int col0 = blockIdx.x * 128;
    const int lr   = tid >> 1;          // 0..127: tile row loaded by this thread
    const int lc   = (tid & 1) << 3;    // 0 or 8: k sub-column base

    const int garow = row0 + lr;
    size_t aoff;
    const float* gbase = nullptr;
    if (MODE == 2) {
        int b = garow / NV;
        int n = garow - b * NV;
        aoff  = ((size_t)b * NTOK + n) * (size_t)K;
        gbase = E0 + b * DM + lc;
    } else {
        aoff = (size_t)garow * (size_t)K;
    }
    const float* Arow = A + aoff + lc;
    const float* Wrow = W + (size_t)(col0 + lr) * (size_t)K + lc;

    float acc[8][8];
#pragma unroll
    for (int i = 0; i < 8; i++)
#pragma unroll
        for (int j = 0; j < 8; j++) acc[i][j] = 0.f;

    const int tr = (tid >> 4) << 3;   // output row base within tile
    const int tc = (tid & 15) << 3;   // output col base within tile

    const int NT = K >> 4;            // 16-wide k tiles

    float4 pa0, pa1, pb0, pb1;

    // ---- load tile 0 into registers, stage into buffer 0 ----
    pa0 = *reinterpret_cast<const float4*>(Arow + 0);
    pa1 = *reinterpret_cast<const float4*>(Arow + 4);
    pb0 = *reinterpret_cast<const float4*>(Wrow + 0);
    pb1 = *reinterpret_cast<const float4*>(Wrow + 4);
    if (MODE == 2) {
        float4 g0 = *reinterpret_cast<const float4*>(gbase + 0);
        float4 g1 = *reinterpret_cast<const float4*>(gbase + 4);
        pa0.x *= g0.x; pa0.y *= g0.y; pa0.z *= g0.z; pa0.w *= g0.w;
        pa1.x *= g1.x; pa1.y *= g1.y; pa1.z *= g1.z; pa1.w *= g1.w;
    }
    {
        As[0][lc + 0][lr] = pa0.x; As[0][lc + 1][lr] = pa0.y;
        As[0][lc + 2][lr] = pa0.z; As[0][lc + 3][lr] = pa0.w;
        As[0][lc + 4][lr] = pa1.x; As[0][lc + 5][lr] = pa1.y;
        As[0][lc + 6][lr] = pa1.z; As[0][lc + 7][lr] = pa1.w;
        Bs[0][lc + 0][lr] = pb0.x; Bs[0][lc + 1][lr] = pb0.y;
        Bs[0][lc + 2][lr] = pb0.z; Bs[0][lc + 3][lr] = pb0.w;
        Bs[0][lc + 4][lr] = pb1.x; Bs[0][lc + 5][lr] = pb1.y;
        Bs[0][lc + 6][lr] = pb1.z; Bs[0][lc + 7][lr] = pb1.w;
    }
    __syncthreads();

    for (int t = 0; t < NT; t++) {
        const int buf = t & 1;

        // prefetch next k-tile into registers (overlaps with compute below)
        if (t + 1 < NT) {
            const int k0 = (t + 1) << 4;
            pa0 = *reinterpret_cast<const float4*>(Arow + k0 + 0);
            pa1 = *reinterpret_cast<const float4*>(Arow + k0 + 4);
            pb0 = *reinterpret_cast<const float4*>(Wrow + k0 + 0);
            pb1 = *reinterpret_cast<const float4*>(Wrow + k0 + 4);
            if (MODE == 2) {
                float4 g0 = *reinterpret_cast<const float4*>(gbase + k0 + 0);
                float4 g1 = *reinterpret_cast<const float4*>(gbase + k0 + 4);
                pa0.x *= g0.x; pa0.y *= g0.y; pa0.z *= g0.z; pa0.w *= g0.w;
                pa1.x *= g1.x; pa1.y *= g1.y; pa1.z *= g1.z; pa1.w *= g1.w;
            }
        }

#pragma unroll
        for (int kk = 0; kk < 16; kk++) {
            const float4 ra0 = *reinterpret_cast<const float4*>(&As[buf][kk][tr]);
            const float4 ra1 = *reinterpret_cast<const float4*>(&As[buf][kk][tr + 4]);
            const float4 rb0 = *reinterpret_cast<const float4*>(&Bs[buf][kk][tc]);
            const float4 rb1 = *reinterpret_cast<const float4*>(&Bs[buf][kk][tc + 4]);
            const float ra[8] = {ra0.x, ra0.y, ra0.z, ra0.w, ra1.x, ra1.y, ra1.z, ra1.w};
            const float rb[8] = {rb0.x, rb0.y, rb0.z, rb0.w, rb1.x, rb1.y, rb1.z, rb1.w};
#pragma unroll
            for (int i = 0; i < 8; i++)
#pragma unroll
                for (int j = 0; j < 8; j++)
                    acc[i][j] = fmaf(ra[i], rb[j], acc[i][j]);
        }

        if (t + 1 < NT) {
            const int nb = buf ^ 1;   // stage into the other buffer (no hazard)
            As[nb][lc + 0][lr] = pa0.x; As[nb][lc + 1][lr] = pa0.y;
            As[nb][lc + 2][lr] = pa0.z; As[nb][lc + 3][lr] = pa0.w;
            As[nb][lc + 4][lr] = pa1.x; As[nb][lc + 5][lr] = pa1.y;
            As[nb][lc + 6][lr] = pa1.z; As[nb][lc + 7][lr] = pa1.w;
            Bs[nb][lc + 0][lr] = pb0.x; Bs[nb][lc + 1][lr] = pb0.y;
            Bs[nb][lc + 2][lr] = pb0.z; Bs[nb][lc + 3][lr] = pb0.w;
            Bs[nb][lc + 4][lr] = pb1.x; Bs[nb][lc + 5][lr] = pb1.y;
            Bs[nb][lc + 6][lr] = pb1.z; Bs[nb][lc + 7][lr] = pb1.w;
            __syncthreads();
        }
    }

#pragma unroll
    for (int i = 0; i < 8; i++) {
        const int m = row0 + tr + i;
        size_t crow;
        int eb = 0, en = 0;
        if (MODE == 0) {
            int b = m >> 8;           // NI = 256
            int n = m & 255;
            crow = (size_t)b * NTOK + NV + n;
        } else if (MODE == 2) {
            eb = m / NV; en = m - eb * NV;
            crow = (size_t)m;
        } else {
            crow = (size_t)m;
        }
#pragma unroll
        for (int j = 0; j < 8; j += 4) {
            const int col = col0 + tc + j;
            const float4 bb = *reinterpret_cast<const float4*>(bias + col);
            float4 v;
            v.x = acc[i][j + 0] + bb.x;
            v.y = acc[i][j + 1] + bb.y;
            v.z = acc[i][j + 2] + bb.z;
            v.w = acc[i][j + 3] + bb.w;
            if (MODE == 2) {
                const float4 q4 = *reinterpret_cast<const float4*>(
                    E1 + ((size_t)eb * NTOK + en) * DM + col);
                v.x += q4.x; v.y += q4.y; v.z += q4.z; v.w += q4.w;
            }
            if (MODE == 3) {
                const float4 r4 = *reinterpret_cast<const float4*>(
                    E0 + (size_t)m * DM + col);
                v.x += r4.x; v.y += r4.y; v.z += r4.z; v.w += r4.w;
            }
            *reinterpret_cast<float4*>(C + crow * DM + col) = v;
        }
    }
}

// ---------------------------------------------------------------------------
// Row-wise L2 normalization, one warp per 512-float row. grid.y selects Q/K.
// ---------------------------------------------------------------------------
__global__ void __launch_bounds__(256) norm_k(float* __restrict__ Q, float* __restrict__ Kb) {
    const int gw   = (blockIdx.x * 256 + threadIdx.x) >> 5;
    const int lane = threadIdx.x & 31;
    if (gw >= BATCH * NTOK) return;
    float* buf = blockIdx.y ? Kb : Q;
    float4* row = reinterpret_cast<float4*>(buf + (size_t)gw * DM);
    float4 v[4];
    float ss = 0.f;
#pragma unroll
    for (int i = 0; i < 4; i++) {
        v[i] = row[lane + 32 * i];
        ss += v[i].x * v[i].x + v[i].y * v[i].y + v[i].z * v[i].z + v[i].w * v[i].w;
    }
#pragma unroll
    for (int o = 16; o; o >>= 1) ss += __shfl_xor_sync(0xffffffffu, ss, o);
    const float inv = 1.f / fmaxf(sqrtf(ss), 1e-12f);
#pragma unroll
    for (int i = 0; i < 4; i++) {
        v[i].x *= inv; v[i].y *= inv; v[i].z *= inv; v[i].w *= inv;
        row[lane + 32 * i] = v[i];
    }
}

// ---------------------------------------------------------------------------
// Per-batch: a = softmax((q @ w_g) * SCALE) over tokens; g = sum_n a[n]*q[n,:].
// One block of 512 threads per batch (d = tid in phase 3).
// ---------------------------------------------------------------------------
__global__ void __launch_bounds__(512) attn_k(const float* __restrict__ Q,
                                              const float* __restrict__ wg,
                                              float* __restrict__ G) {
    __shared__ float sd[NTOK];
    __shared__ float swg[DM];
    __shared__ float red[32];
    const int b    = blockIdx.x;
    const int tid  = threadIdx.x;
    const int warp = tid >> 5;
    const int lane = tid & 31;

    swg[tid] = wg[tid];
    __syncthreads();

    const float* Qb = Q + (size_t)b * NTOK * DM;

    // dots: one warp per row
    for (int n = warp; n < NTOK; n += 16) {
        const float* r = Qb + (size_t)n * DM;
        float s = 0.f;
#pragma unroll
        for (int i = 0; i < 16; i++) s += r[lane + 32 * i] * swg[lane + 32 * i];
#pragma unroll
        for (int o = 16; o; o >>= 1) s += __shfl_xor_sync(0xffffffffu, s, o);
        if (lane == 0) sd[n] = s * SOFTMAX_SCALE;
    }
    __syncthreads();

    // block max
    float m = -1e30f;
    for (int n = tid; n < NTOK; n += 512) m = fmaxf(m, sd[n]);
#pragma unroll
    for (int o = 16; o; o >>= 1) m = fmaxf(m, __shfl_xor_sync(0xffffffffu, m, o));
    if (lane == 0) red[warp] = m;
    __syncthreads();
    if (tid < 32) {
        float t = (tid < 16) ? red[tid] : -1e30f;
#pragma unroll
        for (int o = 8; o; o >>= 1) t = fmaxf(t, __shfl_xor_sync(0xffffffffu, t, o));
        if (tid == 0) red[16] = t;
    }
    __syncthreads();
    m = red[16];

    // exp + block sum
    float s = 0.f;
    for (int n = tid; n < NTOK; n += 512) {
        float e = expf(sd[n] - m);
        sd[n] = e;
        s += e;
    }
#pragma unroll
    for (int o = 16; o; o >>= 1) s += __shfl_xor_sync(0xffffffffu, s, o);
    if (lane == 0) red[warp] = s;
    __syncthreads();
    if (tid < 32) {
        float t = (tid < 16) ? red[tid] : 0.f;
#pragma unroll
        for (int o = 8; o; o >>= 1) t += __shfl_xor_sync(0xffffffffu, t, o);
        if (tid == 0) red[17] = t;
    }
    __syncthreads();
    const float inv = 1.f / red[17];

    // g[b, tid] = sum_n a[n] * Q[b, n, tid]   (coalesced column walk)
    float a0 = 0.f, a1 = 0.f, a2 = 0.f, a3 = 0.f;
    int n = 0;
    for (; n + 4 <= NTOK; n += 4) {
        a0 += sd[n + 0] * Qb[(size_t)(n + 0) * DM + tid];
        a1 += sd[n + 1] * Qb[(size_t)(n + 1) * DM + tid];
        a2 += sd[n + 2] * Qb[(size_t)(n + 2) * DM + tid];
        a3 += sd[n + 3] * Qb[(size_t)(n + 3) * DM + tid];
    }
    for (; n < NTOK; n++) a0 += sd[n] * Qb[(size_t)n * DM + tid];
    G[b * DM + tid] = (a0 + a1 + a2 + a3) * inv;
}

// ---------------------------------------------------------------------------
// Launch pipeline (graph-capturable: kernels only).
// ---------------------------------------------------------------------------
extern "C" void kernel_launch(void* const* d_in, const int* in_sizes, int n_in,
                              void* d_out, int out_size) {
    const float* verts   = (const float*)d_in[0];
    const float* imgf    = (const float*)d_in[1];
    const float* fc_w    = (const float*)d_in[2];
    const float* fc_b    = (const float*)d_in[3];
    const float* q_w     = (const float*)d_in[4];
    const float* q_b     = (const float*)d_in[5];
    const float* k_w     = (const float*)d_in[6];
    const float* k_b     = (const float*)d_in[7];
    const float* w_g     = (const float*)d_in[8];
    const float* proj_w  = (const float*)d_in[9];
    const float* proj_b  = (const float*)d_in[10];
    const float* final_w = (const float*)d_in[11];
    const float* final_b = (const float*)d_in[12];
    float* out = (float*)d_out;

    float *X, *Q, *K, *G;
    cudaGetSymbolAddress((void**)&X, g_X);
    cudaGetSymbolAddress((void**)&Q, g_Q);
    cudaGetSymbolAddress((void**)&K, g_K);
    cudaGetSymbolAddress((void**)&G, g_G);

    // x = concat(verts_f, img_f @ fc_w^T + fc_b)
    copy_verts_k<<<(BATCH * NV * (DM / 4) + 255) / 256, 256>>>(verts);
    gemm_k<0><<<dim3(4, (BATCH * NI) / 128), 256>>>(imgf, fc_w, fc_b, X, IMGD, nullptr, nullptr);

    // q, k projections over all tokens
    gemm_k<1><<<dim3(4, (BATCH * NTOK) / 128), 256>>>(X, q_w, q_b, Q, DM, nullptr, nullptr);
    gemm_k<1><<<dim3(4, (BATCH * NTOK) / 128), 256>>>(X, k_w, k_b, K, DM, nullptr, nullptr);

    // l2norm rows of Q and K in place
    norm_k<<<dim3((BATCH * NTOK) / 8, 2), 256>>>(Q, K);

    // softmax over tokens + global query g
    attn_k<<<BATCH, 512>>>(Q, w_g, G);

    // out = (g*k) @ proj_w^T + proj_b + q   (only vertex-token rows needed
    // downstream); result written compactly into X (x is dead now)
    gemm_k<2><<<dim3(4, (BATCH * NV) / 128), 256>>>(K, proj_w, proj_b, X, DM, G, Q);

    // final = out @ final_w^T + final_b + verts_f  -> d_out
    gemm_k<3><<<dim3(4, (BATCH * NV) / 128), 256>>>(X, final_w, final_b, out, DM, verts, nullptr);
}

// round 8
// speedup vs baseline: 1.8721x; 1.8721x over previous
#include <cuda_runtime.h>
#include <math.h>
#include <stdint.h>

#define BATCH 32
#define NV 1556
#define NI 256
#define NTOK 1812      // NV + NI
#define DM 512
#define IMGD 2048

#define SOFTMAX_SCALE 0.088388347648318440550f  // (512/4)^-0.5

// ---------------------------------------------------------------------------
// Device-global scratch (no runtime allocation allowed).
// ---------------------------------------------------------------------------
__device__ float g_X[BATCH * NTOK * DM];
__device__ float g_Q[BATCH * NTOK * DM];
__device__ float g_K[BATCH * NTOK * DM];
__device__ float g_G[BATCH * DM];

// ---------------------------------------------------------------------------
// PTX helpers — baseline sm_103 only (NO tcgen05 / 'a'-suffix features).
// ---------------------------------------------------------------------------
__device__ __forceinline__ uint32_t smem_u32(const void* p) {
    uint32_t a;
    asm("{ .reg .u64 t; cvta.to.shared.u64 t, %1; cvt.u32.u64 %0, t; }"
        : "=r"(a) : "l"(p));
    return a;
}

__device__ __forceinline__ uint32_t to_tf32(float f) {
    uint32_t u;
    asm("cvt.rna.tf32.f32 %0, %1;" : "=r"(u) : "f"(f));
    return u;
}

#define LDMATRIX_X4(r0, r1, r2, r3, addr) \
    asm volatile("ldmatrix.sync.aligned.m8n8.x4.shared.b16 {%0,%1,%2,%3}, [%4];" \
                 : "=r"(r0), "=r"(r1), "=r"(r2), "=r"(r3) : "r"(addr))

#define MMA_TF32(c, a, b) \
    asm volatile("mma.sync.aligned.m16n8k8.row.col.f32.tf32.tf32.f32 " \
                 "{%0,%1,%2,%3}, {%4,%5,%6,%7}, {%8,%9}, {%0,%1,%2,%3};" \
                 : "+f"((c)[0]), "+f"((c)[1]), "+f"((c)[2]), "+f"((c)[3]) \
                 : "r"((a)[0]), "r"((a)[1]), "r"((a)[2]), "r"((a)[3]), \
                   "r"((b)[0]), "r"((b)[1]))

// ---------------------------------------------------------------------------
// tf32 mma.sync GEMM: C[M, 512] = A[M, K] @ W[512, K]^T + bias (+ epilogues)
//   MODE 0: A = img_f; C rows remapped into X's img-token slots.
//   MODE 1: plain (q / k projections).
//   MODE 2: A row remap b*NTOK+n, A scaled by g[b][:] (E0); epilogue += Q (E1).
//   MODE 3: epilogue += verts residual (E0); C = d_out.
// Block tile 128x128, BK=32, 256 threads (8 warps as 4M x 2N, warp = 32x64).
// Double-buffered smem, register prefetch, tf32 converted on the store path.
// ---------------------------------------------------------------------------
#define SM_STRIDE 36                 // 32 k-words + 4 pad (bank stagger)
#define SM_TILE   (128 * SM_STRIDE)  // words per tile buffer
#define SMEM_MMA  (4 * SM_TILE * 4)  // A[2] + B[2], bytes = 73728

template <int MODE>
__global__ void __launch_bounds__(256, 1) mma_gemm_k(
    const float* __restrict__ A, const float* __restrict__ W,
    const float* __restrict__ bias, float* __restrict__ C, int K,
    const float* __restrict__ E0, const float* __restrict__ E1)
{
    extern __shared__ uint32_t sm[];   // [A0 | A1 | B0 | B1], SM_TILE words each

    const int tid  = threadIdx.x;
    const int warp = tid >> 5;
    const int lane = tid & 31;
    const int row0 = blockIdx.y * 128;
    const int col0 = blockIdx.x * 128;

    // ---- global load addressing: thread -> (tile row lr, k-quarter lq) ----
    const int lr = tid >> 1;            // 0..127
    const int lq = (tid & 1) * 4;       // float4 index base within 8-wide row

    const int garow = row0 + lr;
    size_t aoff;
    const float* gbase = nullptr;
    if (MODE == 2) {
        const int b = garow / NV;
        const int n = garow - b * NV;
        aoff  = ((size_t)b * NTOK + n) * (size_t)K;
        gbase = E0 + (size_t)b * DM;
    } else {
        aoff = (size_t)garow * (size_t)K;
    }
    const float* Arow = A + aoff;
    const float* Wrow = W + (size_t)(col0 + lr) * (size_t)K;

    // ---- warp tiling: 4 (M) x 2 (N); warp tile 32x64 ----
    const int wm = warp >> 1;
    const int wn = warp & 1;

    // ldmatrix per-lane source rows/cols (32-bit element matrices)
    const int arow_l = (lane & 7) + ((lane >> 3) & 1) * 8;   // A: m-row pattern
    const int acol_l = (lane >> 4) * 4;                       // A: k sub-col
    const int brow_l = (lane & 7) + ((lane >> 4) & 1) * 8;   // B: n-row pattern
    const int bcol_l = ((lane >> 3) & 1) * 4;                 // B: k sub-col

    float acc[2][8][4];
#pragma unroll
    for (int mt = 0; mt < 2; mt++)
#pragma unroll
        for (int nt = 0; nt < 8; nt++)
#pragma unroll
            for (int r = 0; r < 4; r++) acc[mt][nt][r] = 0.f;

    const int NT = K >> 5;     // 32-wide k tiles

    float4 va[4], vb[4];

    // ---- load tile 0 into registers ----
#pragma unroll
    for (int i = 0; i < 4; i++) {
        const int kk = (lq + i) * 4;
        va[i] = *reinterpret_cast<const float4*>(Arow + kk);
        vb[i] = *reinterpret_cast<const float4*>(Wrow + kk);
        if (MODE == 2) {
            const float4 g4 = *reinterpret_cast<const float4*>(gbase + kk);
            va[i].x *= g4.x; va[i].y *= g4.y; va[i].z *= g4.z; va[i].w *= g4.w;
        }
    }
    // stage into buffer 0 (tf32 convert)
    {
        uint32_t* As = sm + 0 * SM_TILE + lr * SM_STRIDE;
        uint32_t* Bs = sm + 2 * SM_TILE + lr * SM_STRIDE;
#pragma unroll
        for (int i = 0; i < 4; i++) {
            const int kk = (lq + i) * 4;
            As[kk + 0] = to_tf32(va[i].x); As[kk + 1] = to_tf32(va[i].y);
            As[kk + 2] = to_tf32(va[i].z); As[kk + 3] = to_tf32(va[i].w);
            Bs[kk + 0] = to_tf32(vb[i].x); Bs[kk + 1] = to_tf32(vb[i].y);
            Bs[kk + 2] = to_tf32(vb[i].z); Bs[kk + 3] = to_tf32(vb[i].w);
        }
    }
    __syncthreads();

    for (int t = 0; t < NT; t++) {
        const int buf = t & 1;

        // prefetch next k-tile into registers
        if (t + 1 < NT) {
            const int kb = (t + 1) << 5;
#pragma unroll
            for (int i = 0; i < 4; i++) {
                const int kk = kb + (lq + i) * 4;
                va[i] = *reinterpret_cast<const float4*>(Arow + kk);
                vb[i] = *reinterpret_cast<const float4*>(Wrow + kk);
                if (MODE == 2) {
                    const float4 g4 = *reinterpret_cast<const float4*>(gbase + kk);
                    va[i].x *= g4.x; va[i].y *= g4.y;
                    va[i].z *= g4.z; va[i].w *= g4.w;
                }
            }
        }

        // ---- compute on current buffer ----
        const uint32_t abase = smem_u32(sm + buf * SM_TILE);
        const uint32_t bbase = smem_u32(sm + (2 + buf) * SM_TILE);
#pragma unroll
        for (int ks = 0; ks < 4; ks++) {
            const int k0 = ks * 8;
            uint32_t af[2][4];
#pragma unroll
            for (int mt = 0; mt < 2; mt++) {
                const uint32_t ad = abase +
                    ((wm * 32 + mt * 16 + arow_l) * SM_STRIDE + k0 + acol_l) * 4;
                LDMATRIX_X4(af[mt][0], af[mt][1], af[mt][2], af[mt][3], ad);
            }
            uint32_t bf[8][2];
#pragma unroll
            for (int np = 0; np < 4; np++) {
                uint32_t r0, r1, r2, r3;
                const uint32_t bd = bbase +
                    ((wn * 64 + np * 16 + brow_l) * SM_STRIDE + k0 + bcol_l) * 4;
                LDMATRIX_X4(r0, r1, r2, r3, bd);
                bf[np * 2 + 0][0] = r0; bf[np * 2 + 0][1] = r1;
                bf[np * 2 + 1][0] = r2; bf[np * 2 + 1][1] = r3;
            }
#pragma unroll
            for (int mt = 0; mt < 2; mt++)
#pragma unroll
                for (int nt = 0; nt < 8; nt++)
                    MMA_TF32(acc[mt][nt], af[mt], bf[nt]);
        }

        // ---- stage prefetched tile into the other buffer ----
        if (t + 1 < NT) {
            const int nb = buf ^ 1;
            uint32_t* As = sm + nb * SM_TILE + lr * SM_STRIDE;
            uint32_t* Bs = sm + (2 + nb) * SM_TILE + lr * SM_STRIDE;
#pragma unroll
            for (int i = 0; i < 4; i++) {
                const int kk = (lq + i) * 4;
                As[kk + 0] = to_tf32(va[i].x); As[kk + 1] = to_tf32(va[i].y);
                As[kk + 2] = to_tf32(va[i].z); As[kk + 3] = to_tf32(va[i].w);
                Bs[kk + 0] = to_tf32(vb[i].x); Bs[kk + 1] = to_tf32(vb[i].y);
                Bs[kk + 2] = to_tf32(vb[i].z); Bs[kk + 3] = to_tf32(vb[i].w);
            }
            __syncthreads();
        }
    }

    // ---- epilogue ----
    const int orow  = lane >> 2;        // 0..7
    const int ocol2 = (lane & 3) * 2;   // 0,2,4,6

#pragma unroll
    for (int mt = 0; mt < 2; mt++) {
#pragma unroll
        for (int half = 0; half < 2; half++) {
            const int m = row0 + wm * 32 + mt * 16 + orow + half * 8;
            size_t crow;
            int eb = 0, en = 0;
            if (MODE == 0) {
                const int b = m >> 8;          // NI = 256
                const int n = m & 255;
                crow = (size_t)b * NTOK + NV + n;
            } else if (MODE == 2) {
                eb = m / NV; en = m - eb * NV;
                crow = (size_t)m;
            } else {
                crow = (size_t)m;
            }
#pragma unroll
            for (int nt = 0; nt < 8; nt++) {
                const int col = col0 + wn * 64 + nt * 8 + ocol2;
                float2 v;
                v.x = acc[mt][nt][half * 2 + 0] + bias[col];
                v.y = acc[mt][nt][half * 2 + 1] + bias[col + 1];
                if (MODE == 2) {
                    const float2 q2 = *reinterpret_cast<const float2*>(
                        E1 + ((size_t)eb * NTOK + en) * DM + col);
                    v.x += q2.x; v.y += q2.y;
                }
                if (MODE == 3) {
                    const float2 r2 = *reinterpret_cast<const float2*>(
                        E0 + (size_t)m * DM + col);
                    v.x += r2.x; v.y += r2.y;
                }
                *reinterpret_cast<float2*>(C + crow * DM + col) = v;
            }
        }
    }
}

// ---------------------------------------------------------------------------
// Copy verts_f into the first NV token rows of X (float4 granularity).
// ---------------------------------------------------------------------------
__global__ void __launch_bounds__(256) copy_verts_k(const float* __restrict__ V) {
    size_t i = (size_t)blockIdx.x * 256 + threadIdx.x;
    const size_t tot = (size_t)BATCH * NV * (DM / 4);
    if (i >= tot) return;
    size_t m = i >> 7;
    int c = (int)(i & 127);
    int b = (int)(m / NV);
    int n = (int)(m - (size_t)b * NV);
    reinterpret_cast<float4*>(g_X)[((size_t)b * NTOK + n) * (DM / 4) + c] =
        reinterpret_cast<const float4*>(V)[i];
}

// ---------------------------------------------------------------------------
// Row-wise L2 normalization, one warp per 512-float row. grid.y selects Q/K.
// ---------------------------------------------------------------------------
__global__ void __launch_bounds__(256) norm_k(float* __restrict__ Q, float* __restrict__ Kb) {
    const int gw   = (blockIdx.x * 256 + threadIdx.x) >> 5;
    const int lane = threadIdx.x & 31;
    if (gw >= BATCH * NTOK) return;
    float* buf = blockIdx.y ? Kb : Q;
    float4* row = reinterpret_cast<float4*>(buf + (size_t)gw * DM);
    float4 v[4];
    float ss = 0.f;
#pragma unroll
    for (int i = 0; i < 4; i++) {
        v[i] = row[lane + 32 * i];
        ss += v[i].x * v[i].x + v[i].y * v[i].y + v[i].z * v[i].z + v[i].w * v[i].w;
    }
#pragma unroll
    for (int o = 16; o; o >>= 1) ss += __shfl_xor_sync(0xffffffffu, ss, o);
    const float inv = 1.f / fmaxf(sqrtf(ss), 1e-12f);
#pragma unroll
    for (int i = 0; i < 4; i++) {
        v[i].x *= inv; v[i].y *= inv; v[i].z *= inv; v[i].w *= inv;
        row[lane + 32 * i] = v[i];
    }
}

// ---------------------------------------------------------------------------
// Per-batch: a = softmax((q @ w_g) * SCALE) over tokens; g = sum_n a[n]*q[n,:].
// ---------------------------------------------------------------------------
__global__ void __launch_bounds__(512) attn_k(const float* __restrict__ Q,
                                              const float* __restrict__ wg,
                                              float* __restrict__ G) {
    __shared__ float sd[NTOK];
    __shared__ float swg[DM];
    __shared__ float red[32];
    const int b    = blockIdx.x;
    const int tid  = threadIdx.x;
    const int warp = tid >> 5;
    const int lane = tid & 31;

    swg[tid] = wg[tid];
    __syncthreads();

    const float* Qb = Q + (size_t)b * NTOK * DM;

    for (int n = warp; n < NTOK; n += 16) {
        const float* r = Qb + (size_t)n * DM;
        float s = 0.f;
#pragma unroll
        for (int i = 0; i < 16; i++) s += r[lane + 32 * i] * swg[lane + 32 * i];
#pragma unroll
        for (int o = 16; o; o >>= 1) s += __shfl_xor_sync(0xffffffffu, s, o);
        if (lane == 0) sd[n] = s * SOFTMAX_SCALE;
    }
    __syncthreads();

    float m = -1e30f;
    for (int n = tid; n < NTOK; n += 512) m = fmaxf(m, sd[n]);
#pragma unroll
    for (int o = 16; o; o >>= 1) m = fmaxf(m, __shfl_xor_sync(0xffffffffu, m, o));
    if (lane == 0) red[warp] = m;
    __syncthreads();
    if (tid < 32) {
        float t = (tid < 16) ? red[tid] : -1e30f;
#pragma unroll
        for (int o = 8; o; o >>= 1) t = fmaxf(t, __shfl_xor_sync(0xffffffffu, t, o));
        if (tid == 0) red[16] = t;
    }
    __syncthreads();
    m = red[16];

    float s = 0.f;
    for (int n = tid; n < NTOK; n += 512) {
        float e = expf(sd[n] - m);
        sd[n] = e;
        s += e;
    }
#pragma unroll
    for (int o = 16; o; o >>= 1) s += __shfl_xor_sync(0xffffffffu, s, o);
    if (lane == 0) red[warp] = s;
    __syncthreads();
    if (tid < 32) {
        float t = (tid < 16) ? red[tid] : 0.f;
#pragma unroll
        for (int o = 8; o; o >>= 1) t += __shfl_xor_sync(0xffffffffu, t, o);
        if (tid == 0) red[17] = t;
    }
    __syncthreads();
    const float inv = 1.f / red[17];

    float a0 = 0.f, a1 = 0.f, a2 = 0.f, a3 = 0.f;
    int n = 0;
    for (; n + 4 <= NTOK; n += 4) {
        a0 += sd[n + 0] * Qb[(size_t)(n + 0) * DM + tid];
        a1 += sd[n + 1] * Qb[(size_t)(n + 1) * DM + tid];
        a2 += sd[n + 2] * Qb[(size_t)(n + 2) * DM + tid];
        a3 += sd[n + 3] * Qb[(size_t)(n + 3) * DM + tid];
    }
    for (; n < NTOK; n++) a0 += sd[n] * Qb[(size_t)n * DM + tid];
    G[b * DM + tid] = (a0 + a1 + a2 + a3) * inv;
}

// ---------------------------------------------------------------------------
// Launch pipeline (graph-capturable: kernels only).
// ---------------------------------------------------------------------------
extern "C" void kernel_launch(void* const* d_in, const int* in_sizes, int n_in,
                              void* d_out, int out_size) {
    const float* verts   = (const float*)d_in[0];
    const float* imgf    = (const float*)d_in[1];
    const float* fc_w    = (const float*)d_in[2];
    const float* fc_b    = (const float*)d_in[3];
    const float* q_w     = (const float*)d_in[4];
    const float* q_b     = (const float*)d_in[5];
    const float* k_w     = (const float*)d_in[6];
    const float* k_b     = (const float*)d_in[7];
    const float* w_g     = (const float*)d_in[8];
    const float* proj_w  = (const float*)d_in[9];
    const float* proj_b  = (const float*)d_in[10];
    const float* final_w = (const float*)d_in[11];
    const float* final_b = (const float*)d_in[12];
    float* out = (float*)d_out;

    float *X, *Q, *K, *G;
    cudaGetSymbolAddress((void**)&X, g_X);
    cudaGetSymbolAddress((void**)&Q, g_Q);
    cudaGetSymbolAddress((void**)&K, g_K);
    cudaGetSymbolAddress((void**)&G, g_G);

    cudaFuncSetAttribute(mma_gemm_k<0>, cudaFuncAttributeMaxDynamicSharedMemorySize, SMEM_MMA);
    cudaFuncSetAttribute(mma_gemm_k<1>, cudaFuncAttributeMaxDynamicSharedMemorySize, SMEM_MMA);
    cudaFuncSetAttribute(mma_gemm_k<2>, cudaFuncAttributeMaxDynamicSharedMemorySize, SMEM_MMA);
    cudaFuncSetAttribute(mma_gemm_k<3>, cudaFuncAttributeMaxDynamicSharedMemorySize, SMEM_MMA);

    // x = concat(verts_f, img_f @ fc_w^T + fc_b)
    copy_verts_k<<<(BATCH * NV * (DM / 4) + 255) / 256, 256>>>(verts);
    mma_gemm_k<0><<<dim3(4, (BATCH * NI) / 128), 256, SMEM_MMA>>>(
        imgf, fc_w, fc_b, X, IMGD, nullptr, nullptr);

    // q, k projections over all tokens
    mma_gemm_k<1><<<dim3(4, (BATCH * NTOK) / 128), 256, SMEM_MMA>>>(
        X, q_w, q_b, Q, DM, nullptr, nullptr);
    mma_gemm_k<1><<<dim3(4, (BATCH * NTOK) / 128), 256, SMEM_MMA>>>(
        X, k_w, k_b, K, DM, nullptr, nullptr);

    // l2norm rows of Q and K in place
    norm_k<<<dim3((BATCH * NTOK) / 8, 2), 256>>>(Q, K);

    // softmax over tokens + global query g
    attn_k<<<BATCH, 512>>>(Q, w_g, G);

    // out = (g*k) @ proj_w^T + proj_b + q  (vertex-token rows only, compact in X)
    mma_gemm_k<2><<<dim3(4, (BATCH * NV) / 128), 256, SMEM_MMA>>>(
        K, proj_w, proj_b, X, DM, G, Q);

    // final = out @ final_w^T + final_b + verts_f  -> d_out
    mma_gemm_k<3><<<dim3(4, (BATCH * NV) / 128), 256, SMEM_MMA>>>(
        X, final_w, final_b, out, DM, verts, nullptr);
}

// round 9
// speedup vs baseline: 2.9930x; 1.5987x over previous
#include <cuda_runtime.h>
#include <math.h>
#include <stdint.h>

#define BATCH 32
#define NV 1556
#define NI 256
#define NTOK 1812      // NV + NI
#define DM 512
#define IMGD 2048
#define NSLICE 8
#define SLROWS 227     // ceil(1812/8)

#define SOFTMAX_SCALE 0.088388347648318440550f  // (512/4)^-0.5

// ---------------------------------------------------------------------------
// Device-global scratch (no runtime allocation allowed).
// ---------------------------------------------------------------------------
__device__ float g_X[BATCH * NTOK * DM];   // x; later: compact g*k
__device__ float g_Q[BATCH * NTOK * DM];
__device__ float g_K[BATCH * NTOK * DM];
__device__ float g_P[BATCH * NV * DM];     // proj output (compact)
__device__ float g_G[BATCH * DM];
__device__ float g_L[BATCH * NTOK];        // logits -> softmax weights
__device__ float g_Gp[NSLICE * BATCH * DM];

// ---------------------------------------------------------------------------
// PTX helpers — baseline sm_103 only (no 'a'-suffix features).
// ---------------------------------------------------------------------------
__device__ __forceinline__ uint32_t smem_u32(const void* p) {
    uint32_t a;
    asm("{ .reg .u64 t; cvta.to.shared.u64 t, %1; cvt.u32.u64 %0, t; }"
        : "=r"(a) : "l"(p));
    return a;
}

__device__ __forceinline__ uint32_t cvt_rna(uint32_t x) {
    uint32_t y;
    asm("cvt.rna.tf32.f32 %0, %1;" : "=r"(y) : "f"(__uint_as_float(x)));
    return y;
}

#define CP16(dst, src) \
    asm volatile("cp.async.cg.shared.global [%0], [%1], 16;" \
                 :: "r"(dst), "l"(src))
#define CP_COMMIT() asm volatile("cp.async.commit_group;" ::: "memory")
#define CP_WAIT1()  asm volatile("cp.async.wait_group 1;" ::: "memory")
#define CP_WAIT0()  asm volatile("cp.async.wait_group 0;" ::: "memory")

#define LDMATRIX_X4(r0, r1, r2, r3, addr) \
    asm volatile("ldmatrix.sync.aligned.m8n8.x4.shared.b16 {%0,%1,%2,%3}, [%4];" \
                 : "=r"(r0), "=r"(r1), "=r"(r2), "=r"(r3) : "r"(addr))

#define MMA_TF32(c, a, b) \
    asm volatile("mma.sync.aligned.m16n8k8.row.col.f32.tf32.tf32.f32 " \
                 "{%0,%1,%2,%3}, {%4,%5,%6,%7}, {%8,%9}, {%0,%1,%2,%3};" \
                 : "+f"((c)[0]), "+f"((c)[1]), "+f"((c)[2]), "+f"((c)[3]) \
                 : "r"((a)[0]), "r"((a)[1]), "r"((a)[2]), "r"((a)[3]), \
                   "r"((b)[0]), "r"((b)[1]))

// ---------------------------------------------------------------------------
// cp.async double-buffered tf32 GEMM: C[M,512] = A[M,K] @ W[512,K]^T + bias
//   MODE 0: C rows remapped into X's img-token slots.
//   MODE 1: plain.
//   MODE 2: epilogue += E0 at remapped row (b*NTOK+n)  [E0 = Q].
//   MODE 3: epilogue += E0 at linear row               [E0 = verts].
// Block 128x128, BK=32, 8 warps (4M x 2N), 2 smem stages (XOR-swizzled),
// cvt.rna applied on fragments after ldmatrix (RNA semantics preserved).
// ---------------------------------------------------------------------------
#define STG_BYTES 32768              // (128 A rows + 128 B rows) * 32 f * 4B
#define SMEM_CA   (2 * STG_BYTES)    // 65536

template <int MODE>
__global__ void __launch_bounds__(256, 2) ca_gemm_k(
    const float* __restrict__ A, const float* __restrict__ W,
    const float* __restrict__ bias, float* __restrict__ C, int K,
    const float* __restrict__ E0)
{
    extern __shared__ uint32_t sm[];
    const uint32_t sbase = smem_u32(sm);

    const int tid  = threadIdx.x;
    const int warp = tid >> 5;
    const int lane = tid & 31;
    const int row0 = blockIdx.y * 128;
    const int col0 = blockIdx.x * 128;

    // ---- async-load addressing: thread -> (row lrow, 4 chunks of 16B) ----
    const int lrow   = tid >> 1;          // 0..127
    const int lchunk = (tid & 1) * 4;     // chunk base (8 chunks of 16B / row)
    const int lxor   = lrow & 7;
    const float* Ag = A + (size_t)(row0 + lrow) * (size_t)K;
    const float* Wg = W + (size_t)(col0 + lrow) * (size_t)K;
    const uint32_t srowA = (uint32_t)(lrow << 3);

    // ---- warp tiling: 4 (M) x 2 (N); warp tile 32x64 ----
    const int wm = warp >> 1;
    const int wn = warp & 1;
    const int arow_l = (lane & 7) + ((lane >> 3) & 1) * 8;
    const int brow_l = (lane & 7) + ((lane >> 4) & 1) * 8;
    const int acsel  = lane >> 4;          // 0/1 -> k sub-chunk
    const int bcsel  = (lane >> 3) & 1;
    const int fxor   = lane & 7;           // row&7 for both a and b patterns

    float acc[2][8][4];
#pragma unroll
    for (int mt = 0; mt < 2; mt++)
#pragma unroll
        for (int nt = 0; nt < 8; nt++)
#pragma unroll
            for (int r = 0; r < 4; r++) acc[mt][nt][r] = 0.f;

    const int NT = K >> 5;

    // ---- stage loader ----
    auto stage_load = [&](int t) {
        const uint32_t sb = sbase + (uint32_t)(t & 1) * STG_BYTES;
        const int kof = t << 5;            // t*32 floats
#pragma unroll
        for (int i = 0; i < 4; i++) {
            const int c = lchunk + i;
            CP16(sb + ((srowA + (uint32_t)(c ^ lxor)) << 4), Ag + kof + c * 4);
        }
#pragma unroll
        for (int i = 0; i < 4; i++) {
            const int c = lchunk + i;
            CP16(sb + 16384u + ((srowA + (uint32_t)(c ^ lxor)) << 4),
                 Wg + kof + c * 4);
        }
        CP_COMMIT();
    };

    stage_load(0);
    stage_load(1);

    for (int t = 0; t < NT; t++) {
        if (t < NT - 1) CP_WAIT1(); else CP_WAIT0();
        __syncthreads();

        const uint32_t abase = sbase + (uint32_t)(t & 1) * STG_BYTES;
        const uint32_t bbase = abase + 16384u;

#pragma unroll
        for (int ks = 0; ks < 4; ks++) {
            uint32_t af[2][4];
#pragma unroll
            for (int mt = 0; mt < 2; mt++) {
                const int row = wm * 32 + mt * 16 + arow_l;
                const int chk = (ks * 2 + acsel) ^ fxor;
                const uint32_t ad = abase + (uint32_t)(((row << 3) + chk) << 4);
                LDMATRIX_X4(af[mt][0], af[mt][1], af[mt][2], af[mt][3], ad);
            }
            uint32_t bf[8][2];
#pragma unroll
            for (int np = 0; np < 4; np++) {
                uint32_t r0, r1, r2, r3;
                const int row = wn * 64 + np * 16 + brow_l;
                const int chk = (ks * 2 + bcsel) ^ fxor;
                const uint32_t bd = bbase + (uint32_t)(((row << 3) + chk) << 4);
                LDMATRIX_X4(r0, r1, r2, r3, bd);
                bf[np * 2 + 0][0] = r0; bf[np * 2 + 0][1] = r1;
                bf[np * 2 + 1][0] = r2; bf[np * 2 + 1][1] = r3;
            }
            // RNA tf32 rounding on fragments (keeps fp32->tf32 semantics exact)
#pragma unroll
            for (int mt = 0; mt < 2; mt++)
#pragma unroll
                for (int r = 0; r < 4; r++) af[mt][r] = cvt_rna(af[mt][r]);
#pragma unroll
            for (int nt = 0; nt < 8; nt++) {
                bf[nt][0] = cvt_rna(bf[nt][0]);
                bf[nt][1] = cvt_rna(bf[nt][1]);
            }
#pragma unroll
            for (int mt = 0; mt < 2; mt++)
#pragma unroll
                for (int nt = 0; nt < 8; nt++)
                    MMA_TF32(acc[mt][nt], af[mt], bf[nt]);
        }

        __syncthreads();
        if (t + 2 < NT) stage_load(t + 2);
    }

    // ---- epilogue ----
    const int orow  = lane >> 2;
    const int ocol2 = (lane & 3) * 2;

#pragma unroll
    for (int mt = 0; mt < 2; mt++) {
#pragma unroll
        for (int half = 0; half < 2; half++) {
            const int m = row0 + wm * 32 + mt * 16 + orow + half * 8;
            size_t crow, erow = 0;
            if (MODE == 0) {
                const int b = m >> 8;          // NI = 256
                const int n = m & 255;
                crow = (size_t)b * NTOK + NV + n;
            } else if (MODE == 2) {
                const int b = m / NV;
                const int n = m - b * NV;
                crow = (size_t)m;
                erow = (size_t)b * NTOK + n;
            } else {
                crow = (size_t)m;
                erow = (size_t)m;
            }
#pragma unroll
            for (int nt = 0; nt < 8; nt++) {
                const int col = col0 + wn * 64 + nt * 8 + ocol2;
                float2 v;
                v.x = acc[mt][nt][half * 2 + 0] + bias[col];
                v.y = acc[mt][nt][half * 2 + 1] + bias[col + 1];
                if (MODE == 2 || MODE == 3) {
                    const float2 e2 = *reinterpret_cast<const float2*>(
                        E0 + erow * DM + col);
                    v.x += e2.x; v.y += e2.y;
                }
                *reinterpret_cast<float2*>(C + crow * DM + col) = v;
            }
        }
    }
}

// ---------------------------------------------------------------------------
// Copy verts_f into the first NV token rows of X (float4 granularity).
// ---------------------------------------------------------------------------
__global__ void __launch_bounds__(256) copy_verts_k(const float* __restrict__ V) {
    size_t i = (size_t)blockIdx.x * 256 + threadIdx.x;
    const size_t tot = (size_t)BATCH * NV * (DM / 4);
    if (i >= tot) return;
    size_t m = i >> 7;
    int c = (int)(i & 127);
    int b = (int)(m / NV);
    int n = (int)(m - (size_t)b * NV);
    reinterpret_cast<float4*>(g_X)[((size_t)b * NTOK + n) * (DM / 4) + c] =
        reinterpret_cast<const float4*>(V)[i];
}

// ---------------------------------------------------------------------------
// Row L2 norm (1 warp/row). y=0: Q, also writes logits L = (qn . wg)*SCALE.
// y=1: K.
// ---------------------------------------------------------------------------
__global__ void __launch_bounds__(256) norm_k(float* __restrict__ Q,
                                              float* __restrict__ Kb,
                                              const float* __restrict__ wg,
                                              float* __restrict__ L) {
    const int gw   = (blockIdx.x * 256 + threadIdx.x) >> 5;
    const int lane = threadIdx.x & 31;
    if (gw >= BATCH * NTOK) return;
    const int isQ = (blockIdx.y == 0);
    float* buf = isQ ? Q : Kb;
    float4* row = reinterpret_cast<float4*>(buf + (size_t)gw * DM);
    float4 v[4];
    float ss = 0.f;
#pragma unroll
    for (int i = 0; i < 4; i++) {
        v[i] = row[lane + 32 * i];
        ss += v[i].x * v[i].x + v[i].y * v[i].y + v[i].z * v[i].z + v[i].w * v[i].w;
    }
#pragma unroll
    for (int o = 16; o; o >>= 1) ss += __shfl_xor_sync(0xffffffffu, ss, o);
    const float inv = 1.f / fmaxf(sqrtf(ss), 1e-12f);
    float dot = 0.f;
#pragma unroll
    for (int i = 0; i < 4; i++) {
        v[i].x *= inv; v[i].y *= inv; v[i].z *= inv; v[i].w *= inv;
        row[lane + 32 * i] = v[i];
        if (isQ) {
            const float4 w4 = reinterpret_cast<const float4*>(wg)[lane + 32 * i];
            dot += v[i].x * w4.x + v[i].y * w4.y + v[i].z * w4.z + v[i].w * w4.w;
        }
    }
    if (isQ) {
#pragma unroll
        for (int o = 16; o; o >>= 1) dot += __shfl_xor_sync(0xffffffffu, dot, o);
        if (lane == 0) L[gw] = dot * SOFTMAX_SCALE;
    }
}

// ---------------------------------------------------------------------------
// Per-batch softmax over logits (in place: L -> weights).
// ---------------------------------------------------------------------------
__global__ void __launch_bounds__(512) softmax_k(float* __restrict__ L) {
    __shared__ float sd[NTOK];
    __shared__ float red[32];
    const int b    = blockIdx.x;
    const int tid  = threadIdx.x;
    const int warp = tid >> 5;
    const int lane = tid & 31;
    float* Lb = L + (size_t)b * NTOK;

    for (int n = tid; n < NTOK; n += 512) sd[n] = Lb[n];
    __syncthreads();

    float m = -1e30f;
    for (int n = tid; n < NTOK; n += 512) m = fmaxf(m, sd[n]);
#pragma unroll
    for (int o = 16; o; o >>= 1) m = fmaxf(m, __shfl_xor_sync(0xffffffffu, m, o));
    if (lane == 0) red[warp] = m;
    __syncthreads();
    if (tid < 32) {
        float t = (tid < 16) ? red[tid] : -1e30f;
#pragma unroll
        for (int o = 8; o; o >>= 1) t = fmaxf(t, __shfl_xor_sync(0xffffffffu, t, o));
        if (tid == 0) red[16] = t;
    }
    __syncthreads();
    m = red[16];

    float s = 0.f;
    for (int n = tid; n < NTOK; n += 512) {
        float e = expf(sd[n] - m);
        sd[n] = e;
        s += e;
    }
#pragma unroll
    for (int o = 16; o; o >>= 1) s += __shfl_xor_sync(0xffffffffu, s, o);
    if (lane == 0) red[warp] = s;
    __syncthreads();
    if (tid < 32) {
        float t = (tid < 16) ? red[tid] : 0.f;
#pragma unroll
        for (int o = 8; o; o >>= 1) t += __shfl_xor_sync(0xffffffffu, t, o);
        if (tid == 0) red[17] = t;
    }
    __syncthreads();
    const float inv = 1.f / red[17];
    for (int n = tid; n < NTOK; n += 512) Lb[n] = sd[n] * inv;
}

// ---------------------------------------------------------------------------
// Partial global-query reduce: block (b, s) sums its token slice.
// Deterministic (fixed slicing + fixed-order combine; no atomics).
// ---------------------------------------------------------------------------
__global__ void __launch_bounds__(512) greduce_k(const float* __restrict__ Q,
                                                 const float* __restrict__ L) {
    const int b = blockIdx.x;
    const int s = blockIdx.y;
    const int d = threadIdx.x;
    const int n0 = s * SLROWS;
    const int n1 = (n0 + SLROWS < NTOK) ? n0 + SLROWS : NTOK;
    const float* Qb = Q + (size_t)b * NTOK * DM;
    const float* Lb = L + (size_t)b * NTOK;
    float a = 0.f;
    for (int n = n0; n < n1; n++)
        a += Lb[n] * Qb[(size_t)n * DM + d];
    g_Gp[((size_t)s * BATCH + b) * DM + d] = a;
}

__global__ void __launch_bounds__(512) combine_k() {
    const int b = blockIdx.x;
    const int d = threadIdx.x;
    float a = 0.f;
#pragma unroll
    for (int s = 0; s < NSLICE; s++)
        a += g_Gp[((size_t)s * BATCH + b) * DM + d];
    g_G[(size_t)b * DM + d] = a;
}

// ---------------------------------------------------------------------------
// Compact scaled K: X[b*NV+n, :] = g[b,:] * K[b*NTOK+n, :]
// ---------------------------------------------------------------------------
__global__ void __launch_bounds__(256) scale_k(const float* __restrict__ K4) {
    size_t i = (size_t)blockIdx.x * 256 + threadIdx.x;
    const size_t tot = (size_t)BATCH * NV * (DM / 4);
    if (i >= tot) return;
    size_t m = i >> 7;
    int c = (int)(i & 127);
    int b = (int)(m / NV);
    int n = (int)(m - (size_t)b * NV);
    float4 k4 = reinterpret_cast<const float4*>(K4)[((size_t)b * NTOK + n) * 128 + c];
    const float4 gg = reinterpret_cast<const float4*>(g_G)[(size_t)b * 128 + c];
    k4.x *= gg.x; k4.y *= gg.y; k4.z *= gg.z; k4.w *= gg.w;
    reinterpret_cast<float4*>(g_X)[m * 128 + c] = k4;
}

// ---------------------------------------------------------------------------
// Launch pipeline (graph-capturable: kernels only).
// ---------------------------------------------------------------------------
extern "C" void kernel_launch(void* const* d_in, const int* in_sizes, int n_in,
                              void* d_out, int out_size) {
    const float* verts   = (const float*)d_in[0];
    const float* imgf    = (const float*)d_in[1];
    const float* fc_w    = (const float*)d_in[2];
    const float* fc_b    = (const float*)d_in[3];
    const float* q_w     = (const float*)d_in[4];
    const float* q_b     = (const float*)d_in[5];
    const float* k_w     = (const float*)d_in[6];
    const float* k_b     = (const float*)d_in[7];
    const float* w_g     = (const float*)d_in[8];
    const float* proj_w  = (const float*)d_in[9];
    const float* proj_b  = (const float*)d_in[10];
    const float* final_w = (const float*)d_in[11];
    const float* final_b = (const float*)d_in[12];
    float* out = (float*)d_out;

    float *X, *Q, *K, *P, *L;
    cudaGetSymbolAddress((void**)&X, g_X);
    cudaGetSymbolAddress((void**)&Q, g_Q);
    cudaGetSymbolAddress((void**)&K, g_K);
    cudaGetSymbolAddress((void**)&P, g_P);
    cudaGetSymbolAddress((void**)&L, g_L);

    cudaFuncSetAttribute(ca_gemm_k<0>, cudaFuncAttributeMaxDynamicSharedMemorySize, SMEM_CA);
    cudaFuncSetAttribute(ca_gemm_k<1>, cudaFuncAttributeMaxDynamicSharedMemorySize, SMEM_CA);
    cudaFuncSetAttribute(ca_gemm_k<2>, cudaFuncAttributeMaxDynamicSharedMemorySize, SMEM_CA);
    cudaFuncSetAttribute(ca_gemm_k<3>, cudaFuncAttributeMaxDynamicSharedMemorySize, SMEM_CA);

    // x = concat(verts_f, img_f @ fc_w^T + fc_b)
    copy_verts_k<<<(BATCH * NV * (DM / 4) + 255) / 256, 256>>>(verts);
    ca_gemm_k<0><<<dim3(4, (BATCH * NI) / 128), 256, SMEM_CA>>>(
        imgf, fc_w, fc_b, X, IMGD, nullptr);

    // q, k projections over all tokens
    ca_gemm_k<1><<<dim3(4, (BATCH * NTOK) / 128), 256, SMEM_CA>>>(
        X, q_w, q_b, Q, DM, nullptr);
    ca_gemm_k<1><<<dim3(4, (BATCH * NTOK) / 128), 256, SMEM_CA>>>(
        X, k_w, k_b, K, DM, nullptr);

    // l2norm Q (+ fused attention logits) and K
    norm_k<<<dim3((BATCH * NTOK) / 8, 2), 256>>>(Q, K, w_g, L);

    // softmax over tokens; global query g via deterministic 2-stage reduce
    softmax_k<<<BATCH, 512>>>(L);
    greduce_k<<<dim3(BATCH, NSLICE), 512>>>(Q, L);
    combine_k<<<BATCH, 512>>>();

    // compact scaled K' = g (.) K  -> X (x is dead)
    scale_k<<<(BATCH * NV * (DM / 4) + 255) / 256, 256>>>(K);

    // out = K' @ proj_w^T + proj_b + q   (vertex rows only, compact)
    ca_gemm_k<2><<<dim3(4, (BATCH * NV) / 128), 256, SMEM_CA>>>(
        X, proj_w, proj_b, P, DM, Q);

    // final = out @ final_w^T + final_b + verts_f  -> d_out
    ca_gemm_k<3><<<dim3(4, (BATCH * NV) / 128), 256, SMEM_CA>>>(
        P, final_w, final_b, out, DM, verts);
}

// round 10
// speedup vs baseline: 3.2844x; 1.0974x over previous
#include <cuda_runtime.h>
#include <math.h>
#include <stdint.h>

#define BATCH 32
#define NV 1556
#define NI 256
#define NTOK 1812      // NV + NI
#define DM 512
#define IMGD 2048
#define NSLICE 8
#define SLROWS 227     // ceil(1812/8)

#define SOFTMAX_SCALE 0.088388347648318440550f  // (512/4)^-0.5

// ---------------------------------------------------------------------------
// Device-global scratch (no runtime allocation allowed).
// ---------------------------------------------------------------------------
__device__ float g_X[BATCH * NTOK * DM];   // x; later: compact g*k
__device__ float g_Q[BATCH * NTOK * DM];
__device__ float g_K[BATCH * NTOK * DM];
__device__ float g_P[BATCH * NV * DM];     // proj output (compact)
__device__ float g_G[BATCH * DM];
__device__ float g_L[BATCH * NTOK];        // logits -> softmax weights
__device__ float g_Gp[NSLICE * BATCH * DM];

// ---------------------------------------------------------------------------
// PTX helpers — baseline sm_103 only (no 'a'-suffix features).
// ---------------------------------------------------------------------------
__device__ __forceinline__ uint32_t smem_u32(const void* p) {
    uint32_t a;
    asm("{ .reg .u64 t; cvta.to.shared.u64 t, %1; cvt.u32.u64 %0, t; }"
        : "=r"(a) : "l"(p));
    return a;
}

#define CP16(dst, src) \
    asm volatile("cp.async.cg.shared.global [%0], [%1], 16;" \
                 :: "r"(dst), "l"(src))
#define CP_COMMIT() asm volatile("cp.async.commit_group;" ::: "memory")
#define CP_WAIT1()  asm volatile("cp.async.wait_group 1;" ::: "memory")
#define CP_WAIT0()  asm volatile("cp.async.wait_group 0;" ::: "memory")

#define LDMATRIX_X4(r0, r1, r2, r3, addr) \
    asm volatile("ldmatrix.sync.aligned.m8n8.x4.shared.b16 {%0,%1,%2,%3}, [%4];" \
                 : "=r"(r0), "=r"(r1), "=r"(r2), "=r"(r3) : "r"(addr))

// raw fp32 bits as tf32 operands (round-toward-zero fast path; HW uses the
// high mantissa bits) — removes the per-fragment cvt ALU stream.
#define MMA_TF32(c, a, b) \
    asm volatile("mma.sync.aligned.m16n8k8.row.col.f32.tf32.tf32.f32 " \
                 "{%0,%1,%2,%3}, {%4,%5,%6,%7}, {%8,%9}, {%0,%1,%2,%3};" \
                 : "+f"((c)[0]), "+f"((c)[1]), "+f"((c)[2]), "+f"((c)[3]) \
                 : "r"((a)[0]), "r"((a)[1]), "r"((a)[2]), "r"((a)[3]), \
                   "r"((b)[0]), "r"((b)[1]))

// ---------------------------------------------------------------------------
// cp.async 3-stage tf32 GEMM: C[M,512] = A[M,K] @ W[512,K]^T + bias
//   MODE 0: C rows remapped into X's img-token slots.
//   MODE 1: plain.
//   MODE 2: epilogue += E0 at remapped row (b*NTOK+n)  [E0 = Q].
//   MODE 3: epilogue += E0 at linear row               [E0 = verts].
// Block 128x128, BK=32, 8 warps (4M x 2N), 3 smem stages (XOR-swizzled),
// one __syncthreads per k-tile.
// ---------------------------------------------------------------------------
#define STG_BYTES 32768              // (128 A rows + 128 B rows) * 32 f * 4B
#define SMEM_CA   (3 * STG_BYTES)    // 98304

template <int MODE>
__global__ void __launch_bounds__(256, 2) ca_gemm_k(
    const float* __restrict__ A, const float* __restrict__ W,
    const float* __restrict__ bias, float* __restrict__ C, int K,
    const float* __restrict__ E0)
{
    extern __shared__ uint32_t sm[];
    const uint32_t sbase = smem_u32(sm);

    const int tid  = threadIdx.x;
    const int warp = tid >> 5;
    const int lane = tid & 31;
    const int row0 = blockIdx.y * 128;
    const int col0 = blockIdx.x * 128;

    // ---- async-load addressing: thread -> (row lrow, 4 chunks of 16B) ----
    const int lrow   = tid >> 1;          // 0..127
    const int lchunk = (tid & 1) * 4;     // chunk base (8 chunks of 16B / row)
    const int lxor   = lrow & 7;
    const float* Ag = A + (size_t)(row0 + lrow) * (size_t)K;
    const float* Wg = W + (size_t)(col0 + lrow) * (size_t)K;
    const uint32_t srowA = (uint32_t)(lrow << 3);

    // ---- warp tiling: 4 (M) x 2 (N); warp tile 32x64 ----
    const int wm = warp >> 1;
    const int wn = warp & 1;
    const int arow_l = (lane & 7) + ((lane >> 3) & 1) * 8;
    const int brow_l = (lane & 7) + ((lane >> 4) & 1) * 8;
    const int acsel  = lane >> 4;          // 0/1 -> k sub-chunk
    const int bcsel  = (lane >> 3) & 1;
    const int fxor   = lane & 7;           // row&7 for fragment source rows

    float acc[2][8][4];
#pragma unroll
    for (int mt = 0; mt < 2; mt++)
#pragma unroll
        for (int nt = 0; nt < 8; nt++)
#pragma unroll
            for (int r = 0; r < 4; r++) acc[mt][nt][r] = 0.f;

    const int NT = K >> 5;

    // ---- stage loader (slot = t % 3) ----
    auto stage_load = [&](int t, int slot) {
        const uint32_t sb = sbase + (uint32_t)slot * STG_BYTES;
        const int kof = t << 5;            // t*32 floats
#pragma unroll
        for (int i = 0; i < 4; i++) {
            const int c = lchunk + i;
            CP16(sb + ((srowA + (uint32_t)(c ^ lxor)) << 4), Ag + kof + c * 4);
        }
#pragma unroll
        for (int i = 0; i < 4; i++) {
            const int c = lchunk + i;
            CP16(sb + 16384u + ((srowA + (uint32_t)(c ^ lxor)) << 4),
                 Wg + kof + c * 4);
        }
        CP_COMMIT();
    };

    stage_load(0, 0);
    stage_load(1, 1);

    int slot = 0;                          // t % 3
    for (int t = 0; t < NT; t++) {
        if (t < NT - 1) CP_WAIT1(); else CP_WAIT0();
        __syncthreads();

        const uint32_t abase = sbase + (uint32_t)slot * STG_BYTES;
        const uint32_t bbase = abase + 16384u;

        // prefetch stage t+2 into slot (t+2)%3 == (t-1)%3 (read finished at
        // iteration t-1; protected by the barrier above)
        if (t + 2 < NT) {
            int ps = slot + 2; if (ps >= 3) ps -= 3;
            stage_load(t + 2, ps);
        }

#pragma unroll
        for (int ks = 0; ks < 4; ks++) {
            uint32_t af[2][4];
#pragma unroll
            for (int mt = 0; mt < 2; mt++) {
                const int row = wm * 32 + mt * 16 + arow_l;
                const int chk = (ks * 2 + acsel) ^ fxor;
                const uint32_t ad = abase + (uint32_t)(((row << 3) + chk) << 4);
                LDMATRIX_X4(af[mt][0], af[mt][1], af[mt][2], af[mt][3], ad);
            }
            uint32_t bf[8][2];
#pragma unroll
            for (int np = 0; np < 4; np++) {
                uint32_t r0, r1, r2, r3;
                const int row = wn * 64 + np * 16 + brow_l;
                const int chk = (ks * 2 + bcsel) ^ fxor;
                const uint32_t bd = bbase + (uint32_t)(((row << 3) + chk) << 4);
                LDMATRIX_X4(r0, r1, r2, r3, bd);
                bf[np * 2 + 0][0] = r0; bf[np * 2 + 0][1] = r1;
                bf[np * 2 + 1][0] = r2; bf[np * 2 + 1][1] = r3;
            }
#pragma unroll
            for (int mt = 0; mt < 2; mt++)
#pragma unroll
                for (int nt = 0; nt < 8; nt++)
                    MMA_TF32(acc[mt][nt], af[mt], bf[nt]);
        }

        slot++; if (slot >= 3) slot -= 3;
    }

    // ---- epilogue ----
    const int orow  = lane >> 2;
    const int ocol2 = (lane & 3) * 2;

#pragma unroll
    for (int mt = 0; mt < 2; mt++) {
#pragma unroll
        for (int half = 0; half < 2; half++) {
            const int m = row0 + wm * 32 + mt * 16 + orow + half * 8;
            size_t crow, erow = 0;
            if (MODE == 0) {
                const int b = m >> 8;          // NI = 256
                const int n = m & 255;
                crow = (size_t)b * NTOK + NV + n;
            } else if (MODE == 2) {
                const int b = m / NV;
                const int n = m - b * NV;
                crow = (size_t)m;
                erow = (size_t)b * NTOK + n;
            } else {
                crow = (size_t)m;
                erow = (size_t)m;
            }
#pragma unroll
            for (int nt = 0; nt < 8; nt++) {
                const int col = col0 + wn * 64 + nt * 8 + ocol2;
                float2 v;
                v.x = acc[mt][nt][half * 2 + 0] + bias[col];
                v.y = acc[mt][nt][half * 2 + 1] + bias[col + 1];
                if (MODE == 2 || MODE == 3) {
                    const float2 e2 = *reinterpret_cast<const float2*>(
                        E0 + erow * DM + col);
                    v.x += e2.x; v.y += e2.y;
                }
                *reinterpret_cast<float2*>(C + crow * DM + col) = v;
            }
        }
    }
}

// ---------------------------------------------------------------------------
// Copy verts_f into the first NV token rows of X (float4 granularity).
// ---------------------------------------------------------------------------
__global__ void __launch_bounds__(256) copy_verts_k(const float* __restrict__ V) {
    size_t i = (size_t)blockIdx.x * 256 + threadIdx.x;
    const size_t tot = (size_t)BATCH * NV * (DM / 4);
    if (i >= tot) return;
    size_t m = i >> 7;
    int c = (int)(i & 127);
    int b = (int)(m / NV);
    int n = (int)(m - (size_t)b * NV);
    reinterpret_cast<float4*>(g_X)[((size_t)b * NTOK + n) * (DM / 4) + c] =
        reinterpret_cast<const float4*>(V)[i];
}

// ---------------------------------------------------------------------------
// Row L2 norm (1 warp/row). y=0: Q, also writes logits L = (qn . wg)*SCALE.
// y=1: K.
// ---------------------------------------------------------------------------
__global__ void __launch_bounds__(256) norm_k(float* __restrict__ Q,
                                              float* __restrict__ Kb,
                                              const float* __restrict__ wg,
                                              float* __restrict__ L) {
    const int gw   = (blockIdx.x * 256 + threadIdx.x) >> 5;
    const int lane = threadIdx.x & 31;
    if (gw >= BATCH * NTOK) return;
    const int isQ = (blockIdx.y == 0);
    float* buf = isQ ? Q : Kb;
    float4* row = reinterpret_cast<float4*>(buf + (size_t)gw * DM);
    float4 v[4];
    float ss = 0.f;
#pragma unroll
    for (int i = 0; i < 4; i++) {
        v[i] = row[lane + 32 * i];
        ss += v[i].x * v[i].x + v[i].y * v[i].y + v[i].z * v[i].z + v[i].w * v[i].w;
    }
#pragma unroll
    for (int o = 16; o; o >>= 1) ss += __shfl_xor_sync(0xffffffffu, ss, o);
    const float inv = 1.f / fmaxf(sqrtf(ss), 1e-12f);
    float dot = 0.f;
#pragma unroll
    for (int i = 0; i < 4; i++) {
        v[i].x *= inv; v[i].y *= inv; v[i].z *= inv; v[i].w *= inv;
        row[lane + 32 * i] = v[i];
        if (isQ) {
            const float4 w4 = reinterpret_cast<const float4*>(wg)[lane + 32 * i];
            dot += v[i].x * w4.x + v[i].y * w4.y + v[i].z * w4.z + v[i].w * w4.w;
        }
    }
    if (isQ) {
#pragma unroll
        for (int o = 16; o; o >>= 1) dot += __shfl_xor_sync(0xffffffffu, dot, o);
        if (lane == 0) L[gw] = dot * SOFTMAX_SCALE;
    }
}

// ---------------------------------------------------------------------------
// Per-batch softmax over logits (in place: L -> weights).
// ---------------------------------------------------------------------------
__global__ void __launch_bounds__(512) softmax_k(float* __restrict__ L) {
    __shared__ float sd[NTOK];
    __shared__ float red[32];
    const int b    = blockIdx.x;
    const int tid  = threadIdx.x;
    const int warp = tid >> 5;
    const int lane = tid & 31;
    float* Lb = L + (size_t)b * NTOK;

    for (int n = tid; n < NTOK; n += 512) sd[n] = Lb[n];
    __syncthreads();

    float m = -1e30f;
    for (int n = tid; n < NTOK; n += 512) m = fmaxf(m, sd[n]);
#pragma unroll
    for (int o = 16; o; o >>= 1) m = fmaxf(m, __shfl_xor_sync(0xffffffffu, m, o));
    if (lane == 0) red[warp] = m;
    __syncthreads();
    if (tid < 32) {
        float t = (tid < 16) ? red[tid] : -1e30f;
#pragma unroll
        for (int o = 8; o; o >>= 1) t = fmaxf(t, __shfl_xor_sync(0xffffffffu, t, o));
        if (tid == 0) red[16] = t;
    }
    __syncthreads();
    m = red[16];

    float s = 0.f;
    for (int n = tid; n < NTOK; n += 512) {
        float e = expf(sd[n] - m);
        sd[n] = e;
        s += e;
    }
#pragma unroll
    for (int o = 16; o; o >>= 1) s += __shfl_xor_sync(0xffffffffu, s, o);
    if (lane == 0) red[warp] = s;
    __syncthreads();
    if (tid < 32) {
        float t = (tid < 16) ? red[tid] : 0.f;
#pragma unroll
        for (int o = 8; o; o >>= 1) t += __shfl_xor_sync(0xffffffffu, t, o);
        if (tid == 0) red[17] = t;
    }
    __syncthreads();
    const float inv = 1.f / red[17];
    for (int n = tid; n < NTOK; n += 512) Lb[n] = sd[n] * inv;
}

// ---------------------------------------------------------------------------
// Partial global-query reduce: block (b, s) sums its token slice.
// Deterministic (fixed slicing + fixed-order combine; no atomics).
// ---------------------------------------------------------------------------
__global__ void __launch_bounds__(512) greduce_k(const float* __restrict__ Q,
                                                 const float* __restrict__ L) {
    const int b = blockIdx.x;
    const int s = blockIdx.y;
    const int d = threadIdx.x;
    const int n0 = s * SLROWS;
    const int n1 = (n0 + SLROWS < NTOK) ? n0 + SLROWS : NTOK;
    const float* Qb = Q + (size_t)b * NTOK * DM;
    const float* Lb = L + (size_t)b * NTOK;
    float a = 0.f;
    for (int n = n0; n < n1; n++)
        a += Lb[n] * Qb[(size_t)n * DM + d];
    g_Gp[((size_t)s * BATCH + b) * DM + d] = a;
}

__global__ void __launch_bounds__(512) combine_k() {
    const int b = blockIdx.x;
    const int d = threadIdx.x;
    float a = 0.f;
#pragma unroll
    for (int s = 0; s < NSLICE; s++)
        a += g_Gp[((size_t)s * BATCH + b) * DM + d];
    g_G[(size_t)b * DM + d] = a;
}

// ---------------------------------------------------------------------------
// Compact scaled K: X[b*NV+n, :] = g[b,:] * K[b*NTOK+n, :]
// ---------------------------------------------------------------------------
__global__ void __launch_bounds__(256) scale_k(const float* __restrict__ K4) {
    size_t i = (size_t)blockIdx.x * 256 + threadIdx.x;
    const size_t tot = (size_t)BATCH * NV * (DM / 4);
    if (i >= tot) return;
    size_t m = i >> 7;
    int c = (int)(i & 127);
    int b = (int)(m / NV);
    int n = (int)(m - (size_t)b * NV);
    float4 k4 = reinterpret_cast<const float4*>(K4)[((size_t)b * NTOK + n) * 128 + c];
    const float4 gg = reinterpret_cast<const float4*>(g_G)[(size_t)b * 128 + c];
    k4.x *= gg.x; k4.y *= gg.y; k4.z *= gg.z; k4.w *= gg.w;
    reinterpret_cast<float4*>(g_X)[m * 128 + c] = k4;
}

// ---------------------------------------------------------------------------
// Launch pipeline (graph-capturable: kernels only).
// ---------------------------------------------------------------------------
extern "C" void kernel_launch(void* const* d_in, const int* in_sizes, int n_in,
                              void* d_out, int out_size) {
    const float* verts   = (const float*)d_in[0];
    const float* imgf    = (const float*)d_in[1];
    const float* fc_w    = (const float*)d_in[2];
    const float* fc_b    = (const float*)d_in[3];
    const float* q_w     = (const float*)d_in[4];
    const float* q_b     = (const float*)d_in[5];
    const float* k_w     = (const float*)d_in[6];
    const float* k_b     = (const float*)d_in[7];
    const float* w_g     = (const float*)d_in[8];
    const float* proj_w  = (const float*)d_in[9];
    const float* proj_b  = (const float*)d_in[10];
    const float* final_w = (const float*)d_in[11];
    const float* final_b = (const float*)d_in[12];
    float* out = (float*)d_out;

    float *X, *Q, *K, *P, *L;
    cudaGetSymbolAddress((void**)&X, g_X);
    cudaGetSymbolAddress((void**)&Q, g_Q);
    cudaGetSymbolAddress((void**)&K, g_K);
    cudaGetSymbolAddress((void**)&P, g_P);
    cudaGetSymbolAddress((void**)&L, g_L);

    cudaFuncSetAttribute(ca_gemm_k<0>, cudaFuncAttributeMaxDynamicSharedMemorySize, SMEM_CA);
    cudaFuncSetAttribute(ca_gemm_k<1>, cudaFuncAttributeMaxDynamicSharedMemorySize, SMEM_CA);
    cudaFuncSetAttribute(ca_gemm_k<2>, cudaFuncAttributeMaxDynamicSharedMemorySize, SMEM_CA);
    cudaFuncSetAttribute(ca_gemm_k<3>, cudaFuncAttributeMaxDynamicSharedMemorySize, SMEM_CA);

    // x = concat(verts_f, img_f @ fc_w^T + fc_b)
    copy_verts_k<<<(BATCH * NV * (DM / 4) + 255) / 256, 256>>>(verts);
    ca_gemm_k<0><<<dim3(4, (BATCH * NI) / 128), 256, SMEM_CA>>>(
        imgf, fc_w, fc_b, X, IMGD, nullptr);

    // q, k projections over all tokens
    ca_gemm_k<1><<<dim3(4, (BATCH * NTOK) / 128), 256, SMEM_CA>>>(
        X, q_w, q_b, Q, DM, nullptr);
    ca_gemm_k<1><<<dim3(4, (BATCH * NTOK) / 128), 256, SMEM_CA>>>(
        X, k_w, k_b, K, DM, nullptr);

    // l2norm Q (+ fused attention logits) and K
    norm_k<<<dim3((BATCH * NTOK) / 8, 2), 256>>>(Q, K, w_g, L);

    // softmax over tokens; global query g via deterministic 2-stage reduce
    softmax_k<<<BATCH, 512>>>(L);
    greduce_k<<<dim3(BATCH, NSLICE), 512>>>(Q, L);
    combine_k<<<BATCH, 512>>>();

    // compact scaled K' = g (.) K  -> X (x is dead)
    scale_k<<<(BATCH * NV * (DM / 4) + 255) / 256, 256>>>(K);

    // out = K' @ proj_w^T + proj_b + q   (vertex rows only, compact)
    ca_gemm_k<2><<<dim3(4, (BATCH * NV) / 128), 256, SMEM_CA>>>(
        X, proj_w, proj_b, P, DM, Q);

    // final = out @ final_w^T + final_b + verts_f  -> d_out
    ca_gemm_k<3><<<dim3(4, (BATCH * NV) / 128), 256, SMEM_CA>>>(
        P, final_w, final_b, out, DM, verts);
}

// round 11
// speedup vs baseline: 3.5052x; 1.0672x over previous
#include <cuda_runtime.h>
#include <math.h>
#include <stdint.h>

#define BATCH 32
#define NV 1556
#define NI 256
#define NTOK 1812      // NV + NI
#define DM 512
#define IMGD 2048
#define NSLICE 8
#define SLROWS 227     // ceil(1812/8)
#define MB_PROJ 13     // ceil(NV/128) M-blocks per batch in proj GEMM

#define SOFTMAX_SCALE 0.088388347648318440550f  // (512/4)^-0.5

// ---------------------------------------------------------------------------
// Device-global scratch (no runtime allocation allowed).
// ---------------------------------------------------------------------------
__device__ float  g_Q[BATCH * NTOK * DM];      // raw q (pre-norm)
__device__ float  g_K[BATCH * NTOK * DM];      // raw k (pre-norm)
__device__ float  g_C[BATCH * NI * DM];        // compact img projection
__device__ float  g_P[BATCH * NV * DM];        // proj output (compact)
__device__ float  g_W[BATCH * DM * DM];        // Wg[b] = g_b (.) proj_w
__device__ float  g_G[BATCH * DM];             // global query g
__device__ float  g_L[BATCH * NTOK];           // logits -> a' weights
__device__ float  g_Gp[NSLICE * BATCH * DM];   // greduce partials
__device__ float2 g_PQ[BATCH * NTOK * 4];      // per-colblock (sumsq, dot wg)
__device__ float2 g_PK[BATCH * NTOK * 4];      // per-colblock (sumsq, 0)
__device__ float  g_IQ[BATCH * NTOK];          // 1/||q||
__device__ float  g_IK[BATCH * NTOK];          // 1/||k||

// ---------------------------------------------------------------------------
// PTX helpers — baseline sm_103 only (no 'a'-suffix features).
// ---------------------------------------------------------------------------
__device__ __forceinline__ uint32_t smem_u32(const void* p) {
    uint32_t a;
    asm("{ .reg .u64 t; cvta.to.shared.u64 t, %1; cvt.u32.u64 %0, t; }"
        : "=r"(a) : "l"(p));
    return a;
}

#define CP16(dst, src) \
    asm volatile("cp.async.cg.shared.global [%0], [%1], 16;" \
                 :: "r"(dst), "l"(src))
#define CP_COMMIT() asm volatile("cp.async.commit_group;" ::: "memory")
#define CP_WAIT1()  asm volatile("cp.async.wait_group 1;" ::: "memory")
#define CP_WAIT0()  asm volatile("cp.async.wait_group 0;" ::: "memory")

#define LDMATRIX_X4(r0, r1, r2, r3, addr) \
    asm volatile("ldmatrix.sync.aligned.m8n8.x4.shared.b16 {%0,%1,%2,%3}, [%4];" \
                 : "=r"(r0), "=r"(r1), "=r"(r2), "=r"(r3) : "r"(addr))

// raw fp32 bits as tf32 operands (round-toward-zero fast path).
#define MMA_TF32(c, a, b) \
    asm volatile("mma.sync.aligned.m16n8k8.row.col.f32.tf32.tf32.f32 " \
                 "{%0,%1,%2,%3}, {%4,%5,%6,%7}, {%8,%9}, {%0,%1,%2,%3};" \
                 : "+f"((c)[0]), "+f"((c)[1]), "+f"((c)[2]), "+f"((c)[3]) \
                 : "r"((a)[0]), "r"((a)[1]), "r"((a)[2]), "r"((a)[3]), \
                   "r"((b)[0]), "r"((b)[1]))

// ---------------------------------------------------------------------------
// cp.async 3-stage tf32 GEMM, block 128x128, BK=32, 8 warps (4M x 2N).
//   MODE 0: plain linear A -> linear C             (img_f @ fc_w -> imgC)
//   MODE 1: A row-remap verts/imgC; C=raw Q; epilogue partial (sumsq, q.wg)
//   MODE 2: A row-remap verts/imgC; C=raw K; epilogue partial (sumsq, 0)
//   MODE 3: per-batch (grid.z=b): A=raw K rows (clamped), W=Wg[b];
//           epi: v = inv_k*acc + proj_b + inv_q*q_raw -> P compact
//   MODE 4: linear; epi += verts residual -> d_out
// ---------------------------------------------------------------------------
#define STG_BYTES 32768
#define SMEM_CA   (3 * STG_BYTES)    // 98304

template <int MODE>
__global__ void __launch_bounds__(256, 2) ca_gemm_k(
    const float* __restrict__ A, const float* __restrict__ A2,
    const float* __restrict__ W, const float* __restrict__ bias,
    float* __restrict__ C, int K,
    const float* __restrict__ E0, const float* __restrict__ E1,
    float2* __restrict__ PP)
{
    extern __shared__ uint32_t sm[];
    __shared__ float2 sred[128][2];
    const uint32_t sbase = smem_u32(sm);

    const int tid  = threadIdx.x;
    const int warp = tid >> 5;
    const int lane = tid & 31;
    const int row0 = blockIdx.y * 128;
    const int col0 = blockIdx.x * 128;
    const int bz   = (MODE == 3) ? blockIdx.z : 0;

    // ---- async-load addressing ----
    const int lrow   = tid >> 1;
    const int lchunk = (tid & 1) * 4;
    const int lxor   = lrow & 7;
    const int garow  = row0 + lrow;

    const float* Ag;
    if (MODE == 1 || MODE == 2) {
        const int b = garow / NTOK;
        const int n = garow - b * NTOK;
        Ag = (n < NV) ? A  + ((size_t)b * NV + n) * (size_t)K
                      : A2 + ((size_t)b * NI + (n - NV)) * (size_t)K;
    } else if (MODE == 3) {
        const int n = (garow < NV) ? garow : (NV - 1);
        Ag = A + ((size_t)bz * NTOK + n) * (size_t)K;
    } else {
        Ag = A + (size_t)garow * (size_t)K;
    }
    const float* Wg = ((MODE == 3) ? (W + (size_t)bz * DM * DM) : W)
                      + (size_t)(col0 + lrow) * (size_t)K;
    const uint32_t srowA = (uint32_t)(lrow << 3);

    // ---- warp tiling ----
    const int wm = warp >> 1;
    const int wn = warp & 1;
    const int arow_l = (lane & 7) + ((lane >> 3) & 1) * 8;
    const int brow_l = (lane & 7) + ((lane >> 4) & 1) * 8;
    const int acsel  = lane >> 4;
    const int bcsel  = (lane >> 3) & 1;
    const int fxor   = lane & 7;

    float acc[2][8][4];
#pragma unroll
    for (int mt = 0; mt < 2; mt++)
#pragma unroll
        for (int nt = 0; nt < 8; nt++)
#pragma unroll
            for (int r = 0; r < 4; r++) acc[mt][nt][r] = 0.f;

    const int NT = K >> 5;

    auto stage_load = [&](int t, int slot) {
        const uint32_t sb = sbase + (uint32_t)slot * STG_BYTES;
        const int kof = t << 5;
#pragma unroll
        for (int i = 0; i < 4; i++) {
            const int c = lchunk + i;
            CP16(sb + ((srowA + (uint32_t)(c ^ lxor)) << 4), Ag + kof + c * 4);
        }
#pragma unroll
        for (int i = 0; i < 4; i++) {
            const int c = lchunk + i;
            CP16(sb + 16384u + ((srowA + (uint32_t)(c ^ lxor)) << 4),
                 Wg + kof + c * 4);
        }
        CP_COMMIT();
    };

    stage_load(0, 0);
    stage_load(1, 1);

    int slot = 0;
    for (int t = 0; t < NT; t++) {
        if (t < NT - 1) CP_WAIT1(); else CP_WAIT0();
        __syncthreads();

        const uint32_t abase = sbase + (uint32_t)slot * STG_BYTES;
        const uint32_t bbase = abase + 16384u;

        if (t + 2 < NT) {
            int ps = slot + 2; if (ps >= 3) ps -= 3;
            stage_load(t + 2, ps);
        }

#pragma unroll
        for (int ks = 0; ks < 4; ks++) {
            uint32_t af[2][4];
#pragma unroll
            for (int mt = 0; mt < 2; mt++) {
                const int row = wm * 32 + mt * 16 + arow_l;
                const int chk = (ks * 2 + acsel) ^ fxor;
                const uint32_t ad = abase + (uint32_t)(((row << 3) + chk) << 4);
                LDMATRIX_X4(af[mt][0], af[mt][1], af[mt][2], af[mt][3], ad);
            }
            uint32_t bf[8][2];
#pragma unroll
            for (int np = 0; np < 4; np++) {
                uint32_t r0, r1, r2, r3;
                const int row = wn * 64 + np * 16 + brow_l;
                const int chk = (ks * 2 + bcsel) ^ fxor;
                const uint32_t bd = bbase + (uint32_t)(((row << 3) + chk) << 4);
                LDMATRIX_X4(r0, r1, r2, r3, bd);
                bf[np * 2 + 0][0] = r0; bf[np * 2 + 0][1] = r1;
                bf[np * 2 + 1][0] = r2; bf[np * 2 + 1][1] = r3;
            }
#pragma unroll
            for (int mt = 0; mt < 2; mt++)
#pragma unroll
                for (int nt = 0; nt < 8; nt++)
                    MMA_TF32(acc[mt][nt], af[mt], bf[nt]);
        }

        slot++; if (slot >= 3) slot -= 3;
    }

    // ---- epilogue ----
    const int orow  = lane >> 2;
    const int ocol2 = (lane & 3) * 2;

    float pss[2][2], pdot[2][2];
    if (MODE == 1 || MODE == 2) {
#pragma unroll
        for (int a = 0; a < 2; a++)
#pragma unroll
            for (int h = 0; h < 2; h++) { pss[a][h] = 0.f; pdot[a][h] = 0.f; }
    }

#pragma unroll
    for (int mt = 0; mt < 2; mt++) {
#pragma unroll
        for (int half = 0; half < 2; half++) {
            const int m = row0 + wm * 32 + mt * 16 + orow + half * 8;
            size_t crow = (size_t)m;
            size_t tok = 0;
            bool live = true;
            if (MODE == 3) {
                if (m >= NV) live = false;
                tok  = (size_t)bz * NTOK + m;
                crow = (size_t)bz * NV + m;
            }
            float ik = 1.f, iq = 0.f;
            if (MODE == 3 && live) { ik = E0[tok]; iq = E1[tok]; }
#pragma unroll
            for (int nt = 0; nt < 8; nt++) {
                const int col = col0 + wn * 64 + nt * 8 + ocol2;
                float2 v;
                if (MODE == 3) {
                    v.x = ik * acc[mt][nt][half * 2 + 0] + bias[col];
                    v.y = ik * acc[mt][nt][half * 2 + 1] + bias[col + 1];
                    if (live) {
                        const float2 q2 = *reinterpret_cast<const float2*>(
                            A2 + tok * DM + col);
                        v.x += iq * q2.x; v.y += iq * q2.y;
                    }
                } else {
                    v.x = acc[mt][nt][half * 2 + 0] + bias[col];
                    v.y = acc[mt][nt][half * 2 + 1] + bias[col + 1];
                    if (MODE == 4) {
                        const float2 r2 = *reinterpret_cast<const float2*>(
                            E0 + (size_t)m * DM + col);
                        v.x += r2.x; v.y += r2.y;
                    }
                }
                if (MODE == 1 || MODE == 2) {
                    pss[mt][half] += v.x * v.x + v.y * v.y;
                    if (MODE == 1) {
                        pdot[mt][half] += v.x * __ldg(E0 + col)
                                        + v.y * __ldg(E0 + col + 1);
                    }
                }
                if (live)
                    *reinterpret_cast<float2*>(C + crow * DM + col) = v;
            }
        }
    }

    // ---- per-row partial reduction (MODE 1/2) ----
    if (MODE == 1 || MODE == 2) {
#pragma unroll
        for (int off = 1; off <= 2; off <<= 1) {
#pragma unroll
            for (int a = 0; a < 2; a++)
#pragma unroll
                for (int h = 0; h < 2; h++) {
                    pss[a][h]  += __shfl_xor_sync(0xffffffffu, pss[a][h],  off);
                    pdot[a][h] += __shfl_xor_sync(0xffffffffu, pdot[a][h], off);
                }
        }
        if ((lane & 3) == 0) {
#pragma unroll
            for (int a = 0; a < 2; a++)
#pragma unroll
                for (int h = 0; h < 2; h++) {
                    const int rib = wm * 32 + a * 16 + orow + h * 8;
                    sred[rib][wn] = make_float2(pss[a][h], pdot[a][h]);
                }
        }
        __syncthreads();
        if (tid < 128) {
            const float2 u0 = sred[tid][0];
            const float2 u1 = sred[tid][1];
            PP[(size_t)(row0 + tid) * 4 + blockIdx.x] =
                make_float2(u0.x + u1.x, u0.y + u1.y);
        }
    }
}

// ---------------------------------------------------------------------------
// Reduce per-colblock partials -> inv_q, inv_k, logits.
// ---------------------------------------------------------------------------
__global__ void __launch_bounds__(256) invlog_k() {
    const int t = blockIdx.x * 256 + threadIdx.x;
    if (t >= BATCH * NTOK) return;
    float ssq = 0.f, dot = 0.f, ssk = 0.f;
#pragma unroll
    for (int i = 0; i < 4; i++) {
        const float2 pq = g_PQ[(size_t)t * 4 + i];
        ssq += pq.x; dot += pq.y;
        ssk += g_PK[(size_t)t * 4 + i].x;
    }
    const float iq = 1.f / fmaxf(sqrtf(ssq), 1e-12f);
    g_IQ[t] = iq;
    g_IK[t] = 1.f / fmaxf(sqrtf(ssk), 1e-12f);
    g_L[t]  = dot * iq * SOFTMAX_SCALE;
}

// ---------------------------------------------------------------------------
// Per-batch softmax over logits; output a'[n] = softmax[n] * inv_q[n].
// ---------------------------------------------------------------------------
__global__ void __launch_bounds__(512) softmax_k() {
    __shared__ float sd[NTOK];
    __shared__ float red[32];
    const int b    = blockIdx.x;
    const int tid  = threadIdx.x;
    const int warp = tid >> 5;
    const int lane = tid & 31;
    float* Lb = g_L + (size_t)b * NTOK;

    for (int n = tid; n < NTOK; n += 512) sd[n] = Lb[n];
    __syncthreads();

    float m = -1e30f;
    for (int n = tid; n < NTOK; n += 512) m = fmaxf(m, sd[n]);
#pragma unroll
    for (int o = 16; o; o >>= 1) m = fmaxf(m, __shfl_xor_sync(0xffffffffu, m, o));
    if (lane == 0) red[warp] = m;
    __syncthreads();
    if (tid < 32) {
        float t = (tid < 16) ? red[tid] : -1e30f;
#pragma unroll
        for (int o = 8; o; o >>= 1) t = fmaxf(t, __shfl_xor_sync(0xffffffffu, t, o));
        if (tid == 0) red[16] = t;
    }
    __syncthreads();
    m = red[16];

    float s = 0.f;
    for (int n = tid; n < NTOK; n += 512) {
        float e = expf(sd[n] - m);
        sd[n] = e;
        s += e;
    }
#pragma unroll
    for (int o = 16; o; o >>= 1) s += __shfl_xor_sync(0xffffffffu, s, o);
    if (lane == 0) red[warp] = s;
    __syncthreads();
    if (tid < 32) {
        float t = (tid < 16) ? red[tid] : 0.f;
#pragma unroll
        for (int o = 8; o; o >>= 1) t += __shfl_xor_sync(0xffffffffu, t, o);
        if (tid == 0) red[17] = t;
    }
    __syncthreads();
    const float inv = 1.f / red[17];
    for (int n = tid; n < NTOK; n += 512)
        Lb[n] = sd[n] * inv * g_IQ[(size_t)b * NTOK + n];
}

// ---------------------------------------------------------------------------
// g = sum_n a'[n] * Q_raw[n,:]  (deterministic two-stage reduce)
// ---------------------------------------------------------------------------
__global__ void __launch_bounds__(512) greduce_k() {
    const int b = blockIdx.x;
    const int s = blockIdx.y;
    const int d = threadIdx.x;
    const int n0 = s * SLROWS;
    const int n1 = (n0 + SLROWS < NTOK) ? n0 + SLROWS : NTOK;
    const float* Qb = g_Q + (size_t)b * NTOK * DM;
    const float* Lb = g_L + (size_t)b * NTOK;
    float a = 0.f;
    for (int n = n0; n < n1; n++)
        a += Lb[n] * Qb[(size_t)n * DM + d];
    g_Gp[((size_t)s * BATCH + b) * DM + d] = a;
}

__global__ void __launch_bounds__(512) combine_k() {
    const int b = blockIdx.x;
    const int d = threadIdx.x;
    float a = 0.f;
#pragma unroll
    for (int s = 0; s < NSLICE; s++)
        a += g_Gp[((size_t)s * BATCH + b) * DM + d];
    g_G[(size_t)b * DM + d] = a;
}

// ---------------------------------------------------------------------------
// Wg[b] = g_b (.) proj_w   (float4 elementwise)
// ---------------------------------------------------------------------------
__global__ void __launch_bounds__(256) wgscale_k(const float* __restrict__ PW) {
    const size_t i = (size_t)blockIdx.x * 256 + threadIdx.x;   // float4 idx
    const size_t per_b = (size_t)DM * DM / 4;                  // 65536
    if (i >= (size_t)BATCH * per_b) return;
    const size_t b = i / per_b;
    const size_t r = i - b * per_b;
    float4 w = reinterpret_cast<const float4*>(PW)[r];
    const float4 gg = reinterpret_cast<const float4*>(g_G)[b * (DM / 4) + (r & (DM / 4 - 1))];
    w.x *= gg.x; w.y *= gg.y; w.z *= gg.z; w.w *= gg.w;
    reinterpret_cast<float4*>(g_W)[i] = w;
}

// ---------------------------------------------------------------------------
// Launch pipeline (graph-capturable: kernels only).
// ---------------------------------------------------------------------------
extern "C" void kernel_launch(void* const* d_in, const int* in_sizes, int n_in,
                              void* d_out, int out_size) {
    const float* verts   = (const float*)d_in[0];
    const float* imgf    = (const float*)d_in[1];
    const float* fc_w    = (const float*)d_in[2];
    const float* fc_b    = (const float*)d_in[3];
    const float* q_w     = (const float*)d_in[4];
    const float* q_b     = (const float*)d_in[5];
    const float* k_w     = (const float*)d_in[6];
    const float* k_b     = (const float*)d_in[7];
    const float* w_g     = (const float*)d_in[8];
    const float* proj_w  = (const float*)d_in[9];
    const float* proj_b  = (const float*)d_in[10];
    const float* final_w = (const float*)d_in[11];
    const float* final_b = (const float*)d_in[12];
    float* out = (float*)d_out;

    float *Q, *K, *Cimg, *P, *Wg, *IK, *IQ;
    float2 *PQ, *PK;
    cudaGetSymbolAddress((void**)&Q,    g_Q);
    cudaGetSymbolAddress((void**)&K,    g_K);
    cudaGetSymbolAddress((void**)&Cimg, g_C);
    cudaGetSymbolAddress((void**)&P,    g_P);
    cudaGetSymbolAddress((void**)&Wg,   g_W);
    cudaGetSymbolAddress((void**)&IK,   g_IK);
    cudaGetSymbolAddress((void**)&IQ,   g_IQ);
    cudaGetSymbolAddress((void**)&PQ,   g_PQ);
    cudaGetSymbolAddress((void**)&PK,   g_PK);

    cudaFuncSetAttribute(ca_gemm_k<0>, cudaFuncAttributeMaxDynamicSharedMemorySize, SMEM_CA);
    cudaFuncSetAttribute(ca_gemm_k<1>, cudaFuncAttributeMaxDynamicSharedMemorySize, SMEM_CA);
    cudaFuncSetAttribute(ca_gemm_k<2>, cudaFuncAttributeMaxDynamicSharedMemorySize, SMEM_CA);
    cudaFuncSetAttribute(ca_gemm_k<3>, cudaFuncAttributeMaxDynamicSharedMemorySize, SMEM_CA);
    cudaFuncSetAttribute(ca_gemm_k<4>, cudaFuncAttributeMaxDynamicSharedMemorySize, SMEM_CA);

    // imgC = img_f @ fc_w^T + fc_b   (compact [B*NI, DM])
    ca_gemm_k<0><<<dim3(4, (BATCH * NI) / 128), 256, SMEM_CA>>>(
        imgf, nullptr, fc_w, fc_b, Cimg, IMGD, nullptr, nullptr, nullptr);

    // raw q/k over all tokens (A rows remapped from verts/imgC);
    // epilogues write per-colblock (sumsq, dot) partials
    ca_gemm_k<1><<<dim3(4, (BATCH * NTOK) / 128), 256, SMEM_CA>>>(
        verts, Cimg, q_w, q_b, Q, DM, w_g, nullptr, PQ);
    ca_gemm_k<2><<<dim3(4, (BATCH * NTOK) / 128), 256, SMEM_CA>>>(
        verts, Cimg, k_w, k_b, K, DM, nullptr, nullptr, PK);

    // inv norms + logits; softmax -> a' (weights * inv_q); g reduce
    invlog_k<<<(BATCH * NTOK + 255) / 256, 256>>>();
    softmax_k<<<BATCH, 512>>>();
    greduce_k<<<dim3(BATCH, NSLICE), 512>>>();
    combine_k<<<BATCH, 512>>>();

    // per-batch scaled weights Wg[b] = g_b (.) proj_w
    wgscale_k<<<(BATCH * DM * DM / 4 + 255) / 256, 256>>>(proj_w);

    // out = norm(k) @ Wg[b]^T + proj_b + norm(q)   (per-batch tiles, compact P)
    ca_gemm_k<3><<<dim3(4, MB_PROJ, BATCH), 256, SMEM_CA>>>(
        K, Q, Wg, proj_b, P, DM, IK, IQ, nullptr);

    // final = P @ final_w^T + final_b + verts  -> d_out
    ca_gemm_k<4><<<dim3(4, (BATCH * NV) / 128), 256, SMEM_CA>>>(
        P, nullptr, final_w, final_b, out, DM, verts, nullptr, nullptr);
}